// round 16
// baseline (speedup 1.0000x reference)
#include <cuda_runtime.h>
#include <cuda_bf16.h>
#include <cstdint>

// ---------------- problem constants ----------------
#define BATCH 64
#define LSEQ  1024
#define EDIM  320
#define HDIM  480
#define CDIM  32
#define NLAYER 7
#define MTOK  (BATCH*LSEQ)   // 65536
#define ADIM  512            // augmented matrix size (481 used, padded)
#define MS    (ADIM*ADIM)    // elements per slot
#define TREE_CTAS 148

// ---------------- device scratch ----------------
__device__ float          g_bm[NLAYER*HDIM];
__device__ __align__(1024) float g_mat[14*MS];
__device__ float          g_ct[EDIM];
__device__ __nv_bfloat16  g_wtb[EDIM*EDIM];
__device__ int            g_cnt = 0;
__device__ int            g_gen = 0;

__device__ __forceinline__ void cp16(uint32_t s, const void* g) {
    asm volatile("cp.async.cg.shared.global [%0], [%1], 16;" :: "r"(s), "l"(g));
}

// ---------------- bm: one CTA per layer, warp-per-row coalesced ----------------
__global__ __launch_bounds__(512) void bm_kernel(
    const float* __restrict__ snr,
    const float* __restrict__ w1, const float* __restrict__ b1,
    const float* __restrict__ w2, const float* __restrict__ b2,
    const float* __restrict__ w3, const float* __restrict__ b3)
{
    const int i = blockIdx.x;
    __shared__ float h1[HDIM];
    __shared__ float h2[HDIM];
    const int tid  = threadIdx.x;
    const int warp = tid >> 5;
    const int lane = tid & 31;
    const float s = snr[0];

    for (int j = tid; j < HDIM; j += 512)
        h1[j] = fmaxf(0.f, s * w1[i*HDIM + j] + b1[i*HDIM + j]);
    __syncthreads();

    for (int j = warp; j < HDIM; j += 16) {
        const float* w = w2 + ((size_t)i*HDIM + j) * HDIM;
        float acc = 0.f;
        for (int k = lane; k < HDIM; k += 32) acc += w[k] * h1[k];
        #pragma unroll
        for (int o = 16; o > 0; o >>= 1) acc += __shfl_xor_sync(0xffffffffu, acc, o);
        if (lane == 0) h2[j] = fmaxf(0.f, acc + b2[i*HDIM + j]);
    }
    __syncthreads();

    for (int j = warp; j < HDIM; j += 16) {
        const float* w = w3 + ((size_t)i*HDIM + j) * HDIM;
        float acc = 0.f;
        for (int k = lane; k < HDIM; k += 32) acc += w[k] * h2[k];
        #pragma unroll
        for (int o = 16; o > 0; o >>= 1) acc += __shfl_xor_sync(0xffffffffu, acc, o);
        if (lane == 0) g_bm[i*HDIM + j] = 1.f / (1.f + expf(-(acc + b3[i*HDIM + j])));
    }
}

// ---------------- persistent tree kernel ----------------
// Phase 0: materialize 8 augmented matrices.  Barrier.
// Phase 1: L1 (4 products, 256 tile jobs).     Barrier.
// Phase 2: L2 (2 products, 128 tile jobs).     Barrier.
// Phase 3: final product -> g_wtb/g_ct (36 jobs).
// grid = 148 CTAs x 256 threads, all resident (72KB dyn smem, occ 1).

__device__ __forceinline__ void grid_bar() {
    __syncthreads();
    if (threadIdx.x == 0) {
        volatile int* vg = &g_gen;
        const int my = *vg;
        __threadfence();
        if (atomicAdd(&g_cnt, 1) == TREE_CTAS - 1) {
            g_cnt = 0;
            __threadfence();
            atomicAdd(&g_gen, 1);
        } else {
            while (*vg == my) { }
        }
    }
    __syncthreads();
}

// one 64x64 output tile of C = A @ B (all operands ADIM-stride fp32)
// fin: write g_wtb/g_ct instead of C.
__device__ void tile64(const float* __restrict__ A, const float* __restrict__ B,
                       float* __restrict__ C, int r0, int c0, int fin, char* smem)
{
    float (*As)[64][36] = (float(*)[64][36])smem;
    float (*Bs)[32][68] = (float(*)[32][68])(smem + 4*64*36*4);
    const int tid = threadIdx.x;
    const int tx = tid & 15;
    const int ty = tid >> 4;
    const uint32_t sA = (uint32_t)__cvta_generic_to_shared(&As[0][0][0]);
    const uint32_t sB = (uint32_t)__cvta_generic_to_shared(&Bs[0][0][0]);

    auto load_st = [&](int kt, int buf) {
        #pragma unroll
        for (int id = tid; id < 512; id += 256) {
            const int row = id >> 3, kc = (id & 7) * 4;
            cp16(sA + ((buf*64 + row)*36 + kc)*4,
                 A + (size_t)(r0 + row) * ADIM + kt*32 + kc);
        }
        #pragma unroll
        for (int id = tid; id < 512; id += 256) {
            const int row = id >> 4, nc = (id & 15) * 4;
            cp16(sB + ((buf*32 + row)*68 + nc)*4,
                 B + (size_t)(kt*32 + row) * ADIM + c0 + nc);
        }
        asm volatile("cp.async.commit_group;");
    };

    float acc[4][4];
    #pragma unroll
    for (int i = 0; i < 4; i++)
        #pragma unroll
        for (int j = 0; j < 4; j++) acc[i][j] = 0.f;

    load_st(0, 0);
    load_st(1, 1);
    load_st(2, 2);

    const int KT = ADIM / 32;          // 16
    for (int kt = 0; kt < KT; kt++) {
        const int rem = KT - 1 - kt;
        if (rem >= 2)      asm volatile("cp.async.wait_group 2;");
        else if (rem == 1) asm volatile("cp.async.wait_group 1;");
        else               asm volatile("cp.async.wait_group 0;");
        __syncthreads();

        if (kt + 3 < KT) load_st(kt + 3, (kt + 3) & 3);

        const int buf = kt & 3;
        #pragma unroll
        for (int k = 0; k < 32; k++) {
            const float4 bv = *(const float4*)&Bs[buf][k][tx*4];
            const float a0 = As[buf][ty*4+0][k];
            const float a1 = As[buf][ty*4+1][k];
            const float a2 = As[buf][ty*4+2][k];
            const float a3 = As[buf][ty*4+3][k];
            acc[0][0] += a0*bv.x; acc[0][1] += a0*bv.y; acc[0][2] += a0*bv.z; acc[0][3] += a0*bv.w;
            acc[1][0] += a1*bv.x; acc[1][1] += a1*bv.y; acc[1][2] += a1*bv.z; acc[1][3] += a1*bv.w;
            acc[2][0] += a2*bv.x; acc[2][1] += a2*bv.y; acc[2][2] += a2*bv.z; acc[2][3] += a2*bv.w;
            acc[3][0] += a3*bv.x; acc[3][1] += a3*bv.y; acc[3][2] += a3*bv.z; acc[3][3] += a3*bv.w;
        }
        __syncthreads();
    }

    if (!fin) {
        #pragma unroll
        for (int i = 0; i < 4; i++) {
            float4 o;
            o.x = acc[i][0]; o.y = acc[i][1]; o.z = acc[i][2]; o.w = acc[i][3];
            *(float4*)(C + (size_t)(r0 + ty*4 + i) * ADIM + c0 + tx*4) = o;
        }
    } else {
        const int c = c0 + tx*4;
        #pragma unroll
        for (int i = 0; i < 4; i++) {
            const int r = r0 + ty*4 + i;
            if (r < EDIM) {
                if (c + 3 < EDIM) {
                    __nv_bfloat162 h0 = __floats2bfloat162_rn(acc[i][0], acc[i][1]);
                    __nv_bfloat162 h1 = __floats2bfloat162_rn(acc[i][2], acc[i][3]);
                    uint2 pk;
                    pk.x = *(const uint32_t*)&h0;
                    pk.y = *(const uint32_t*)&h1;
                    *(uint2*)(&g_wtb[(size_t)r * EDIM + c]) = pk;
                } else if (c == EDIM) {
                    g_ct[r] = acc[i][0];
                }
            }
        }
    }
}

__global__ __launch_bounds__(256) void tree_kernel(
    const float* __restrict__ sm0_w, const float* __restrict__ sm0_b,
    const float* __restrict__ smm_w, const float* __restrict__ smm_b,
    const float* __restrict__ sml_w, const float* __restrict__ sml_b)
{
    extern __shared__ __align__(16) char smem[];
    const int bid = blockIdx.x;

    // ---- phase 0: materialize ----
    {
        const long stride = (long)TREE_CTAS * 256;
        for (long idx = (long)bid * 256 + threadIdx.x; idx < 8L*MS; idx += stride) {
            const int slot = (int)(idx / MS);
            const int e = (int)(idx - (long)slot * MS);
            const int r = e >> 9;
            const int c = e & 511;
            float v = 0.f;
            if (slot == 0) {               // Wl~
                if (r < EDIM) {
                    if (c < HDIM)       v = sml_w[r*HDIM + c];
                    else if (c == HDIM) v = sml_b[r];
                } else if (r == EDIM && c == HDIM) v = 1.f;
            } else if (slot <= 6) {        // A_i~, i = 7-slot
                const int i = 7 - slot;
                if (r < HDIM) {
                    const float g = g_bm[i*HDIM + r];
                    if (c < HDIM)       v = g * smm_w[((size_t)(i-1)*HDIM + r)*HDIM + c];
                    else if (c == HDIM) v = g * smm_b[(i-1)*HDIM + r];
                } else if (r == HDIM && c == HDIM) v = 1.f;
            } else {                       // M0~
                if (r < HDIM) {
                    const float g = g_bm[r];
                    if (c < EDIM)       v = g * sm0_w[r*EDIM + c];
                    else if (c == EDIM) v = g * sm0_b[r];
                } else if (r == HDIM && c == EDIM) v = 1.f;
            }
            g_mat[idx] = v;
        }
    }
    grid_bar();

    // ---- phase 1: L1, 4 products, 256 jobs ----
    for (int job = bid; job < 256; job += TREE_CTAS) {
        const int z = job >> 6, rem = job & 63;
        tile64(g_mat + (size_t)(2*z) * MS, g_mat + (size_t)(2*z+1) * MS,
               g_mat + (size_t)(8+z) * MS,
               (rem >> 3) * 64, (rem & 7) * 64, 0, smem);
    }
    grid_bar();

    // ---- phase 2: L2, 2 products, 128 jobs ----
    for (int job = bid; job < 128; job += TREE_CTAS) {
        const int z = job >> 6, rem = job & 63;
        tile64(g_mat + (size_t)(8+2*z) * MS, g_mat + (size_t)(9+2*z) * MS,
               g_mat + (size_t)(12+z) * MS,
               (rem >> 3) * 64, (rem & 7) * 64, 0, smem);
    }
    grid_bar();

    // ---- phase 3: final, 36 jobs (6x6 covers 321x321 valid region) ----
    for (int job = bid; job < 36; job += TREE_CTAS) {
        tile64(g_mat + (size_t)12 * MS, g_mat + (size_t)13 * MS,
               nullptr, (job / 6) * 64, (job % 6) * 64, 1, smem);
    }
}

// ---------------- fused token kernel (unchanged from round 15) ----------------
#define BK_T 32
#define LDT  40
#define KT_F (EDIM / BK_T)    // 10
#define OFF_MU   0
#define OFF_INV  512
#define OFF_A    1024
#define OFF_B    (OFF_A + KT_F*128*LDT*2)
#define OFF_XG   1024
#define OFF_WH   (OFF_XG + EDIM*132*4)
#define SMEM_F   (OFF_WH + EDIM*CDIM*4)

__device__ __forceinline__ void ldm4(uint32_t a, uint32_t& r0, uint32_t& r1, uint32_t& r2, uint32_t& r3) {
    asm volatile("ldmatrix.sync.aligned.m8n8.x4.shared.b16 {%0,%1,%2,%3}, [%4];"
                 : "=r"(r0), "=r"(r1), "=r"(r2), "=r"(r3) : "r"(a));
}
__device__ __forceinline__ void mma16816(float* c, const uint32_t* a, const uint32_t* b) {
    asm volatile("mma.sync.aligned.m16n8k16.row.col.f32.bf16.bf16.f32 "
                 "{%0,%1,%2,%3}, {%4,%5,%6,%7}, {%8,%9}, {%0,%1,%2,%3};"
                 : "+f"(c[0]), "+f"(c[1]), "+f"(c[2]), "+f"(c[3])
                 : "r"(a[0]), "r"(a[1]), "r"(a[2]), "r"(a[3]), "r"(b[0]), "r"(b[1]));
}

__global__ __launch_bounds__(512, 1) void fused_k(
    const float* __restrict__ x,
    const float* __restrict__ nw, const float* __restrict__ nb,
    const __nv_bfloat16* __restrict__ Wt,
    const float* __restrict__ hw, const float* __restrict__ hb,
    float* __restrict__ out)
{
    extern __shared__ __align__(16) char smem[];
    const uint32_t sbase = (uint32_t)__cvta_generic_to_shared(smem);
    float* s_mu  = (float*)(smem + OFF_MU);
    float* s_inv = (float*)(smem + OFF_INV);
    __nv_bfloat16* s_xn = (__nv_bfloat16*)(smem + OFF_A);
    float* s_xgT = (float*)(smem + OFF_XG);
    float* s_wh  = (float*)(smem + OFF_WH);

    const int tid  = threadIdx.x;
    const int lane = tid & 31;
    const int warp = tid >> 5;
    const size_t row0 = (size_t)blockIdx.x * 128;

    auto load_B = [&](int kt, int buf) {
        const uint32_t sb = sbase + OFF_B + (uint32_t)buf * (EDIM * LDT * 2);
        #pragma unroll
        for (int id = tid; id < EDIM * 4; id += 512) {
            const int r = id >> 2, c = (id & 3) * 8;
            cp16(sb + (r * LDT + c) * 2, Wt + (size_t)r * EDIM + kt * BK_T + c);
        }
        asm volatile("cp.async.commit_group;");
    };
    load_B(0, 0);
    load_B(1, 1);
    load_B(2, 2);

    // ---- phase 1: LayerNorm ----
    {
        #pragma unroll
        for (int r = 0; r < 8; r++) {
            const int row = warp * 8 + r;
            const float* xp = x + (row0 + row) * EDIM;
            float v[10];
            float s = 0.f, s2 = 0.f;
            #pragma unroll
            for (int i = 0; i < 10; i++) {
                v[i] = xp[lane + 32*i];
                s  += v[i];
                s2 += v[i]*v[i];
            }
            #pragma unroll
            for (int o = 16; o > 0; o >>= 1) {
                s  += __shfl_xor_sync(0xffffffffu, s,  o);
                s2 += __shfl_xor_sync(0xffffffffu, s2, o);
            }
            const float mu  = s  * (1.f/EDIM);
            const float var = s2 * (1.f/EDIM) - mu*mu;
            const float inv = 1.f / sqrtf(var + 1e-5f);
            if (lane == 0) { s_mu[row] = mu; s_inv[row] = inv; }
            #pragma unroll
            for (int i = 0; i < 10; i++) {
                const int c = lane + 32*i;
                const float y = (v[i] - mu) * inv * nw[c] + nb[c];
                s_xn[(i*128 + row)*LDT + lane] = __float2bfloat16(y);
            }
        }
    }
    __syncthreads();

    // ---- phase 2: MMA mainloop ----
    const int wr = warp & 3;
    const int wc = warp >> 2;
    float acc[2][10][4];
    #pragma unroll
    for (int mi = 0; mi < 2; mi++)
        #pragma unroll
        for (int ni = 0; ni < 10; ni++)
            #pragma unroll
            for (int e = 0; e < 4; e++) acc[mi][ni][e] = 0.f;

    for (int kt = 0; kt < KT_F; kt++) {
        const int rem = KT_F - 1 - kt;
        if (rem >= 3)      asm volatile("cp.async.wait_group 3;");
        else if (rem == 2) asm volatile("cp.async.wait_group 2;");
        else if (rem == 1) asm volatile("cp.async.wait_group 1;");
        else               asm volatile("cp.async.wait_group 0;");
        __syncthreads();

        if (kt + 3 < KT_F) load_B(kt + 3, (kt + 3) & 3);

        const uint32_t baseA = sbase + OFF_A + (uint32_t)kt * (128 * LDT * 2);
        const uint32_t baseB = sbase + OFF_B + (uint32_t)(kt & 3) * (EDIM * LDT * 2);
        #pragma unroll
        for (int ks = 0; ks < 2; ks++) {
            uint32_t af[2][4];
            #pragma unroll
            for (int mi = 0; mi < 2; mi++) {
                const int row = wr * 32 + mi * 16 + (lane & 15);
                const int col = ks * 16 + (lane >> 4) * 8;
                ldm4(baseA + (row * LDT + col) * 2, af[mi][0], af[mi][1], af[mi][2], af[mi][3]);
            }
            #pragma unroll
            for (int np = 0; np < 5; np++) {
                uint32_t b0, b1, b2, b3;
                const int row = wc * 80 + np * 16 + (lane & 7) + ((lane >> 4) << 3);
                const int col = ks * 16 + (((lane >> 3) & 1) << 3);
                ldm4(baseB + (row * LDT + col) * 2, b0, b1, b2, b3);
                uint32_t bfa[2] = {b0, b1};
                uint32_t bfb[2] = {b2, b3};
                #pragma unroll
                for (int mi = 0; mi < 2; mi++) {
                    mma16816(acc[mi][2*np],   af[mi], bfa);
                    mma16816(acc[mi][2*np+1], af[mi], bfb);
                }
            }
        }
        __syncthreads();
    }

    // ---- phase 3: sigmoid gate -> xg transposed fp32 ----
    {
        const int mb = wr * 32;
        const int nbase = wc * 80;
        #pragma unroll
        for (int ni = 0; ni < 10; ni++) {
            #pragma unroll
            for (int c2 = 0; c2 < 2; c2++) {
                const int n = nbase + ni * 8 + (lane & 3) * 2 + c2;
                const float ctv = g_ct[n];
                const float nwv = nw[n];
                const float nbv = nb[n];
                #pragma unroll
                for (int mi = 0; mi < 2; mi++) {
                    #pragma unroll
                    for (int eh = 0; eh < 2; eh++) {
                        const int m = mb + mi * 16 + (lane >> 2) + eh * 8;
                        const float z = acc[mi][ni][eh * 2 + c2] + ctv;
                        const float sg = 1.f / (1.f + __expf(-z));
                        const float xv = x[(row0 + m) * EDIM + n];
                        const float xn = (xv - s_mu[m]) * s_inv[m] * nwv + nbv;
                        s_xgT[n * 132 + m] = sg * xn;
                    }
                }
            }
        }
    }
    for (int i = tid; i < EDIM * CDIM; i += 512) {
        const int c = i & 31;
        const int k = i >> 5;
        s_wh[k * CDIM + c] = hw[c * EDIM + k];
    }
    __syncthreads();

    // ---- phase 4: head GEMM ----
    {
        const int rg = tid >> 4;
        const int cg = tid & 15;
        float a2[4][2];
        #pragma unroll
        for (int i = 0; i < 4; i++) { a2[i][0] = 0.f; a2[i][1] = 0.f; }
        #pragma unroll 4
        for (int k = 0; k < EDIM; k++) {
            const float4 av = *(const float4*)&s_xgT[k * 132 + rg * 4];
            const float b0 = s_wh[k * CDIM + cg * 2];
            const float b1 = s_wh[k * CDIM + cg * 2 + 1];
            a2[0][0] += av.x * b0; a2[0][1] += av.x * b1;
            a2[1][0] += av.y * b0; a2[1][1] += av.y * b1;
            a2[2][0] += av.z * b0; a2[2][1] += av.z * b1;
            a2[3][0] += av.w * b0; a2[3][1] += av.w * b1;
        }
        const float hb0 = hb[cg * 2];
        const float hb1 = hb[cg * 2 + 1];
        #pragma unroll
        for (int i = 0; i < 4; i++) {
            const size_t m = row0 + rg * 4 + i;
            out[m * CDIM + cg * 2]     = a2[i][0] + hb0;
            out[m * CDIM + cg * 2 + 1] = a2[i][1] + hb1;
        }
    }
}

// ---------------- launch ----------------
extern "C" void kernel_launch(void* const* d_in, const int* in_sizes, int n_in,
                              void* d_out, int out_size)
{
    (void)in_sizes; (void)n_in; (void)out_size;
    const float* x       = (const float*)d_in[0];
    const float* snr     = (const float*)d_in[1];
    const float* norm_w  = (const float*)d_in[2];
    const float* norm_b  = (const float*)d_in[3];
    const float* sm0_w   = (const float*)d_in[4];
    const float* sm0_b   = (const float*)d_in[5];
    const float* smm_w   = (const float*)d_in[6];
    const float* smm_b   = (const float*)d_in[7];
    const float* sml_w   = (const float*)d_in[8];
    const float* sml_b   = (const float*)d_in[9];
    const float* bm_w1   = (const float*)d_in[10];
    const float* bm_b1   = (const float*)d_in[11];
    const float* bm_w2   = (const float*)d_in[12];
    const float* bm_b2   = (const float*)d_in[13];
    const float* bm_w3   = (const float*)d_in[14];
    const float* bm_b3   = (const float*)d_in[15];
    const float* head_w  = (const float*)d_in[16];
    const float* head_b  = (const float*)d_in[17];

    __nv_bfloat16 *p_wtb;
    cudaGetSymbolAddress((void**)&p_wtb, g_wtb);

    constexpr int SMEM_T = 4*64*36*4 + 4*32*68*4;   // 71,680
    cudaFuncSetAttribute(tree_kernel, cudaFuncAttributeMaxDynamicSharedMemorySize, SMEM_T);
    cudaFuncSetAttribute(fused_k,     cudaFuncAttributeMaxDynamicSharedMemorySize, SMEM_F);

    // 1. gate vectors
    bm_kernel<<<NLAYER, 512>>>(snr, bm_w1, bm_b1, bm_w2, bm_b2, bm_w3, bm_b3);
    // 2. persistent tree: materialize + 3 levels, software grid barriers
    tree_kernel<<<TREE_CTAS, 256, SMEM_T>>>(sm0_w, sm0_b, smm_w, smm_b, sml_w, sml_b);
    // 3. fused token kernel: LN + gate GEMM + sigmoid + head
    fused_k<<<MTOK/128, 512, SMEM_F>>>(x, norm_w, norm_b, p_wtb, head_w, head_b,
                                       (float*)d_out);
}

// round 17
// speedup vs baseline: 1.3239x; 1.3239x over previous
#include <cuda_runtime.h>
#include <cuda_bf16.h>
#include <cstdint>

// ---------------- problem constants ----------------
#define BATCH 64
#define LSEQ  1024
#define EDIM  320
#define HDIM  480
#define CDIM  32
#define NLAYER 7
#define MTOK  (BATCH*LSEQ)   // 65536
#define ADIM  512            // augmented matrix size (481 used, padded)
#define MS    (ADIM*ADIM)    // elements per slot

// ---------------- device scratch ----------------
__device__ float          g_bm[NLAYER*HDIM];
__device__ float          g_h2[NLAYER*HDIM];
__device__ __align__(1024) float g_mat[14*MS];
__device__ float          g_ct[EDIM];
__device__ __nv_bfloat16  g_wtb[EDIM*EDIM];

__device__ __forceinline__ void cp16(uint32_t s, const void* g) {
    asm volatile("cp.async.cg.shared.global [%0], [%1], 16;" :: "r"(s), "l"(g));
}

// ---------------- bm stage A: h2 for all layers (wide GEMV) ----------------
// grid = 7 layers x 60 chunks; 256 thr = 8 warps; warp-per-row, 8 rows/CTA.
__global__ __launch_bounds__(256) void bmA_kernel(
    const float* __restrict__ snr,
    const float* __restrict__ w1, const float* __restrict__ b1,
    const float* __restrict__ w2, const float* __restrict__ b2)
{
    const int i     = blockIdx.x / 60;   // layer
    const int chunk = blockIdx.x % 60;
    __shared__ float h1[HDIM];
    const int tid  = threadIdx.x;
    const int warp = tid >> 5;
    const int lane = tid & 31;
    const float s = snr[0];

    for (int j = tid; j < HDIM; j += 256)
        h1[j] = fmaxf(0.f, s * w1[i*HDIM + j] + b1[i*HDIM + j]);
    __syncthreads();

    const int row = chunk * 8 + warp;
    const float* w = w2 + ((size_t)i*HDIM + row) * HDIM;
    float acc = 0.f;
    #pragma unroll
    for (int k = lane; k < HDIM; k += 32) acc += w[k] * h1[k];
    #pragma unroll
    for (int o = 16; o > 0; o >>= 1) acc += __shfl_xor_sync(0xffffffffu, acc, o);
    if (lane == 0)
        g_h2[i*HDIM + row] = fmaxf(0.f, acc + b2[i*HDIM + row]);
}

// ---------------- bm stage B: gates from h2 (wide GEMV + sigmoid) ----------------
__global__ __launch_bounds__(256) void bmB_kernel(
    const float* __restrict__ w3, const float* __restrict__ b3)
{
    const int i     = blockIdx.x / 60;
    const int chunk = blockIdx.x % 60;
    __shared__ float h2[HDIM];
    const int tid  = threadIdx.x;
    const int warp = tid >> 5;
    const int lane = tid & 31;

    for (int j = tid; j < HDIM; j += 256)
        h2[j] = g_h2[i*HDIM + j];
    __syncthreads();

    const int row = chunk * 8 + warp;
    const float* w = w3 + ((size_t)i*HDIM + row) * HDIM;
    float acc = 0.f;
    #pragma unroll
    for (int k = lane; k < HDIM; k += 32) acc += w[k] * h2[k];
    #pragma unroll
    for (int o = 16; o > 0; o >>= 1) acc += __shfl_xor_sync(0xffffffffu, acc, o);
    if (lane == 0)
        g_bm[i*HDIM + row] = 1.f / (1.f + expf(-(acc + b3[i*HDIM + row])));
}

// ---------------- materialize the 8 augmented matrices ----------------
__global__ void materialize_kernel(
    const float* __restrict__ sm0_w, const float* __restrict__ sm0_b,
    const float* __restrict__ smm_w, const float* __restrict__ smm_b,
    const float* __restrict__ sml_w, const float* __restrict__ sml_b)
{
    const long stride = (long)gridDim.x * blockDim.x;
    for (long idx = (long)blockIdx.x * blockDim.x + threadIdx.x; idx < 8L*MS; idx += stride) {
        const int slot = (int)(idx / MS);
        const int e = (int)(idx - (long)slot * MS);
        const int r = e >> 9;
        const int c = e & 511;
        float v = 0.f;
        if (slot == 0) {               // Wl~
            if (r < EDIM) {
                if (c < HDIM)       v = sml_w[r*HDIM + c];
                else if (c == HDIM) v = sml_b[r];
            } else if (r == EDIM && c == HDIM) v = 1.f;
        } else if (slot <= 6) {        // A_i~, i = 7-slot
            const int i = 7 - slot;
            if (r < HDIM) {
                const float g = g_bm[i*HDIM + r];
                if (c < HDIM)       v = g * smm_w[((size_t)(i-1)*HDIM + r)*HDIM + c];
                else if (c == HDIM) v = g * smm_b[(i-1)*HDIM + r];
            } else if (r == HDIM && c == HDIM) v = 1.f;
        } else {                       // M0~
            if (r < HDIM) {
                const float g = g_bm[r];
                if (c < EDIM)       v = g * sm0_w[r*EDIM + c];
                else if (c == EDIM) v = g * sm0_b[r];
            } else if (r == HDIM && c == EDIM) v = 1.f;
        }
        g_mat[idx] = v;
    }
}

// ---------------- batched 512x512x512 fp32 GEMM (tree) ----------------
#define MM_STG 4
template<int FIN>
__global__ __launch_bounds__(256) void mm3(
    const float* __restrict__ Ab, int Asz,
    const float* __restrict__ Bb, int Bsz,
    float* __restrict__ Cb, int Csz)
{
    const float* A = Ab + (size_t)blockIdx.z * Asz;
    const float* B = Bb + (size_t)blockIdx.z * Bsz;
    float*       C = Cb + (size_t)blockIdx.z * Csz;

    __shared__ __align__(16) float As[MM_STG][64][36];
    __shared__ __align__(16) float Bs[MM_STG][32][68];

    const int tid = threadIdx.x;
    const int tx = tid & 15;
    const int ty = tid >> 4;
    const int r0 = blockIdx.y * 64, c0 = blockIdx.x * 64;

    const uint32_t sA = (uint32_t)__cvta_generic_to_shared(&As[0][0][0]);
    const uint32_t sB = (uint32_t)__cvta_generic_to_shared(&Bs[0][0][0]);

    auto load_st = [&](int kt, int buf) {
        #pragma unroll
        for (int id = tid; id < 512; id += 256) {
            const int row = id >> 3, kc = (id & 7) * 4;
            cp16(sA + ((buf*64 + row)*36 + kc)*4,
                 A + (size_t)(r0 + row) * ADIM + kt*32 + kc);
        }
        #pragma unroll
        for (int id = tid; id < 512; id += 256) {
            const int row = id >> 4, nc = (id & 15) * 4;
            cp16(sB + ((buf*32 + row)*68 + nc)*4,
                 B + (size_t)(kt*32 + row) * ADIM + c0 + nc);
        }
        asm volatile("cp.async.commit_group;");
    };

    float acc[4][4];
    #pragma unroll
    for (int i = 0; i < 4; i++)
        #pragma unroll
        for (int j = 0; j < 4; j++) acc[i][j] = 0.f;

    load_st(0, 0);
    load_st(1, 1);
    load_st(2, 2);

    const int KT = ADIM / 32;          // 16
    for (int kt = 0; kt < KT; kt++) {
        const int rem = KT - 1 - kt;
        if (rem >= 2)      asm volatile("cp.async.wait_group 2;");
        else if (rem == 1) asm volatile("cp.async.wait_group 1;");
        else               asm volatile("cp.async.wait_group 0;");
        __syncthreads();

        if (kt + 3 < KT) load_st(kt + 3, (kt + 3) & 3);

        const int buf = kt & 3;
        #pragma unroll
        for (int k = 0; k < 32; k++) {
            const float4 bv = *(const float4*)&Bs[buf][k][tx*4];
            const float a0 = As[buf][ty*4+0][k];
            const float a1 = As[buf][ty*4+1][k];
            const float a2 = As[buf][ty*4+2][k];
            const float a3 = As[buf][ty*4+3][k];
            acc[0][0] += a0*bv.x; acc[0][1] += a0*bv.y; acc[0][2] += a0*bv.z; acc[0][3] += a0*bv.w;
            acc[1][0] += a1*bv.x; acc[1][1] += a1*bv.y; acc[1][2] += a1*bv.z; acc[1][3] += a1*bv.w;
            acc[2][0] += a2*bv.x; acc[2][1] += a2*bv.y; acc[2][2] += a2*bv.z; acc[2][3] += a2*bv.w;
            acc[3][0] += a3*bv.x; acc[3][1] += a3*bv.y; acc[3][2] += a3*bv.z; acc[3][3] += a3*bv.w;
        }
        __syncthreads();
    }

    if (FIN == 0) {
        #pragma unroll
        for (int i = 0; i < 4; i++) {
            float4 o;
            o.x = acc[i][0]; o.y = acc[i][1]; o.z = acc[i][2]; o.w = acc[i][3];
            *(float4*)(C + (size_t)(r0 + ty*4 + i) * ADIM + c0 + tx*4) = o;
        }
    } else {
        const int c = c0 + tx*4;
        #pragma unroll
        for (int i = 0; i < 4; i++) {
            const int r = r0 + ty*4 + i;
            if (r < EDIM) {
                if (c + 3 < EDIM) {
                    __nv_bfloat162 h0 = __floats2bfloat162_rn(acc[i][0], acc[i][1]);
                    __nv_bfloat162 h1 = __floats2bfloat162_rn(acc[i][2], acc[i][3]);
                    uint2 pk;
                    pk.x = *(const uint32_t*)&h0;
                    pk.y = *(const uint32_t*)&h1;
                    *(uint2*)(&g_wtb[(size_t)r * EDIM + c]) = pk;
                } else if (c == EDIM) {
                    g_ct[r] = acc[i][0];
                }
            }
        }
    }
}

// ---------------- fused token kernel (unchanged from round 15) ----------------
#define BK_T 32
#define LDT  40
#define KT_F (EDIM / BK_T)    // 10
#define OFF_MU   0
#define OFF_INV  512
#define OFF_A    1024
#define OFF_B    (OFF_A + KT_F*128*LDT*2)
#define OFF_XG   1024
#define OFF_WH   (OFF_XG + EDIM*132*4)
#define SMEM_F   (OFF_WH + EDIM*CDIM*4)

__device__ __forceinline__ void ldm4(uint32_t a, uint32_t& r0, uint32_t& r1, uint32_t& r2, uint32_t& r3) {
    asm volatile("ldmatrix.sync.aligned.m8n8.x4.shared.b16 {%0,%1,%2,%3}, [%4];"
                 : "=r"(r0), "=r"(r1), "=r"(r2), "=r"(r3) : "r"(a));
}
__device__ __forceinline__ void mma16816(float* c, const uint32_t* a, const uint32_t* b) {
    asm volatile("mma.sync.aligned.m16n8k16.row.col.f32.bf16.bf16.f32 "
                 "{%0,%1,%2,%3}, {%4,%5,%6,%7}, {%8,%9}, {%0,%1,%2,%3};"
                 : "+f"(c[0]), "+f"(c[1]), "+f"(c[2]), "+f"(c[3])
                 : "r"(a[0]), "r"(a[1]), "r"(a[2]), "r"(a[3]), "r"(b[0]), "r"(b[1]));
}

__global__ __launch_bounds__(512, 1) void fused_k(
    const float* __restrict__ x,
    const float* __restrict__ nw, const float* __restrict__ nb,
    const __nv_bfloat16* __restrict__ Wt,
    const float* __restrict__ hw, const float* __restrict__ hb,
    float* __restrict__ out)
{
    extern __shared__ __align__(16) char smem[];
    const uint32_t sbase = (uint32_t)__cvta_generic_to_shared(smem);
    float* s_mu  = (float*)(smem + OFF_MU);
    float* s_inv = (float*)(smem + OFF_INV);
    __nv_bfloat16* s_xn = (__nv_bfloat16*)(smem + OFF_A);
    float* s_xgT = (float*)(smem + OFF_XG);
    float* s_wh  = (float*)(smem + OFF_WH);

    const int tid  = threadIdx.x;
    const int lane = tid & 31;
    const int warp = tid >> 5;
    const size_t row0 = (size_t)blockIdx.x * 128;

    auto load_B = [&](int kt, int buf) {
        const uint32_t sb = sbase + OFF_B + (uint32_t)buf * (EDIM * LDT * 2);
        #pragma unroll
        for (int id = tid; id < EDIM * 4; id += 512) {
            const int r = id >> 2, c = (id & 3) * 8;
            cp16(sb + (r * LDT + c) * 2, Wt + (size_t)r * EDIM + kt * BK_T + c);
        }
        asm volatile("cp.async.commit_group;");
    };
    load_B(0, 0);
    load_B(1, 1);
    load_B(2, 2);

    // ---- phase 1: LayerNorm ----
    {
        #pragma unroll
        for (int r = 0; r < 8; r++) {
            const int row = warp * 8 + r;
            const float* xp = x + (row0 + row) * EDIM;
            float v[10];
            float s = 0.f, s2 = 0.f;
            #pragma unroll
            for (int i = 0; i < 10; i++) {
                v[i] = xp[lane + 32*i];
                s  += v[i];
                s2 += v[i]*v[i];
            }
            #pragma unroll
            for (int o = 16; o > 0; o >>= 1) {
                s  += __shfl_xor_sync(0xffffffffu, s,  o);
                s2 += __shfl_xor_sync(0xffffffffu, s2, o);
            }
            const float mu  = s  * (1.f/EDIM);
            const float var = s2 * (1.f/EDIM) - mu*mu;
            const float inv = 1.f / sqrtf(var + 1e-5f);
            if (lane == 0) { s_mu[row] = mu; s_inv[row] = inv; }
            #pragma unroll
            for (int i = 0; i < 10; i++) {
                const int c = lane + 32*i;
                const float y = (v[i] - mu) * inv * nw[c] + nb[c];
                s_xn[(i*128 + row)*LDT + lane] = __float2bfloat16(y);
            }
        }
    }
    __syncthreads();

    // ---- phase 2: MMA mainloop ----
    const int wr = warp & 3;
    const int wc = warp >> 2;
    float acc[2][10][4];
    #pragma unroll
    for (int mi = 0; mi < 2; mi++)
        #pragma unroll
        for (int ni = 0; ni < 10; ni++)
            #pragma unroll
            for (int e = 0; e < 4; e++) acc[mi][ni][e] = 0.f;

    for (int kt = 0; kt < KT_F; kt++) {
        const int rem = KT_F - 1 - kt;
        if (rem >= 3)      asm volatile("cp.async.wait_group 3;");
        else if (rem == 2) asm volatile("cp.async.wait_group 2;");
        else if (rem == 1) asm volatile("cp.async.wait_group 1;");
        else               asm volatile("cp.async.wait_group 0;");
        __syncthreads();

        if (kt + 3 < KT_F) load_B(kt + 3, (kt + 3) & 3);

        const uint32_t baseA = sbase + OFF_A + (uint32_t)kt * (128 * LDT * 2);
        const uint32_t baseB = sbase + OFF_B + (uint32_t)(kt & 3) * (EDIM * LDT * 2);
        #pragma unroll
        for (int ks = 0; ks < 2; ks++) {
            uint32_t af[2][4];
            #pragma unroll
            for (int mi = 0; mi < 2; mi++) {
                const int row = wr * 32 + mi * 16 + (lane & 15);
                const int col = ks * 16 + (lane >> 4) * 8;
                ldm4(baseA + (row * LDT + col) * 2, af[mi][0], af[mi][1], af[mi][2], af[mi][3]);
            }
            #pragma unroll
            for (int np = 0; np < 5; np++) {
                uint32_t b0, b1, b2, b3;
                const int row = wc * 80 + np * 16 + (lane & 7) + ((lane >> 4) << 3);
                const int col = ks * 16 + (((lane >> 3) & 1) << 3);
                ldm4(baseB + (row * LDT + col) * 2, b0, b1, b2, b3);
                uint32_t bfa[2] = {b0, b1};
                uint32_t bfb[2] = {b2, b3};
                #pragma unroll
                for (int mi = 0; mi < 2; mi++) {
                    mma16816(acc[mi][2*np],   af[mi], bfa);
                    mma16816(acc[mi][2*np+1], af[mi], bfb);
                }
            }
        }
        __syncthreads();
    }

    // ---- phase 3: sigmoid gate -> xg transposed fp32 ----
    {
        const int mb = wr * 32;
        const int nbase = wc * 80;
        #pragma unroll
        for (int ni = 0; ni < 10; ni++) {
            #pragma unroll
            for (int c2 = 0; c2 < 2; c2++) {
                const int n = nbase + ni * 8 + (lane & 3) * 2 + c2;
                const float ctv = g_ct[n];
                const float nwv = nw[n];
                const float nbv = nb[n];
                #pragma unroll
                for (int mi = 0; mi < 2; mi++) {
                    #pragma unroll
                    for (int eh = 0; eh < 2; eh++) {
                        const int m = mb + mi * 16 + (lane >> 2) + eh * 8;
                        const float z = acc[mi][ni][eh * 2 + c2] + ctv;
                        const float sg = 1.f / (1.f + __expf(-z));
                        const float xv = x[(row0 + m) * EDIM + n];
                        const float xn = (xv - s_mu[m]) * s_inv[m] * nwv + nbv;
                        s_xgT[n * 132 + m] = sg * xn;
                    }
                }
            }
        }
    }
    for (int i = tid; i < EDIM * CDIM; i += 512) {
        const int c = i & 31;
        const int k = i >> 5;
        s_wh[k * CDIM + c] = hw[c * EDIM + k];
    }
    __syncthreads();

    // ---- phase 4: head GEMM ----
    {
        const int rg = tid >> 4;
        const int cg = tid & 15;
        float a2[4][2];
        #pragma unroll
        for (int i = 0; i < 4; i++) { a2[i][0] = 0.f; a2[i][1] = 0.f; }
        #pragma unroll 4
        for (int k = 0; k < EDIM; k++) {
            const float4 av = *(const float4*)&s_xgT[k * 132 + rg * 4];
            const float b0 = s_wh[k * CDIM + cg * 2];
            const float b1 = s_wh[k * CDIM + cg * 2 + 1];
            a2[0][0] += av.x * b0; a2[0][1] += av.x * b1;
            a2[1][0] += av.y * b0; a2[1][1] += av.y * b1;
            a2[2][0] += av.z * b0; a2[2][1] += av.z * b1;
            a2[3][0] += av.w * b0; a2[3][1] += av.w * b1;
        }
        const float hb0 = hb[cg * 2];
        const float hb1 = hb[cg * 2 + 1];
        #pragma unroll
        for (int i = 0; i < 4; i++) {
            const size_t m = row0 + rg * 4 + i;
            out[m * CDIM + cg * 2]     = a2[i][0] + hb0;
            out[m * CDIM + cg * 2 + 1] = a2[i][1] + hb1;
        }
    }
}

// ---------------- launch ----------------
extern "C" void kernel_launch(void* const* d_in, const int* in_sizes, int n_in,
                              void* d_out, int out_size)
{
    (void)in_sizes; (void)n_in; (void)out_size;
    const float* x       = (const float*)d_in[0];
    const float* snr     = (const float*)d_in[1];
    const float* norm_w  = (const float*)d_in[2];
    const float* norm_b  = (const float*)d_in[3];
    const float* sm0_w   = (const float*)d_in[4];
    const float* sm0_b   = (const float*)d_in[5];
    const float* smm_w   = (const float*)d_in[6];
    const float* smm_b   = (const float*)d_in[7];
    const float* sml_w   = (const float*)d_in[8];
    const float* sml_b   = (const float*)d_in[9];
    const float* bm_w1   = (const float*)d_in[10];
    const float* bm_b1   = (const float*)d_in[11];
    const float* bm_w2   = (const float*)d_in[12];
    const float* bm_b2   = (const float*)d_in[13];
    const float* bm_w3   = (const float*)d_in[14];
    const float* bm_b3   = (const float*)d_in[15];
    const float* head_w  = (const float*)d_in[16];
    const float* head_b  = (const float*)d_in[17];

    float *p_mat;
    __nv_bfloat16 *p_wtb;
    cudaGetSymbolAddress((void**)&p_mat, g_mat);
    cudaGetSymbolAddress((void**)&p_wtb, g_wtb);

    cudaFuncSetAttribute(fused_k, cudaFuncAttributeMaxDynamicSharedMemorySize, SMEM_F);

    // ---- token-independent precompute ----
    bmA_kernel<<<NLAYER*60, 256>>>(snr, bm_w1, bm_b1, bm_w2, bm_b2);
    bmB_kernel<<<NLAYER*60, 256>>>(bm_w3, bm_b3);
    materialize_kernel<<<1024, 256>>>(sm0_w, sm0_b, smm_w, smm_b, sml_w, sml_b);

    // ---- balanced-tree composition ----
    mm3<0><<<dim3(ADIM/64, ADIM/64, 4), 256>>>(p_mat + 0*MS, 2*MS, p_mat + 1*MS, 2*MS, p_mat + 8*MS, MS);
    mm3<0><<<dim3(ADIM/64, ADIM/64, 2), 256>>>(p_mat + 8*MS, 2*MS, p_mat + 9*MS, 2*MS, p_mat + 12*MS, MS);
    mm3<1><<<dim3(6, 6, 1), 256>>>(p_mat + 12*MS, 0, p_mat + 13*MS, 0, nullptr, 0);

    // ---- ONE fused token kernel: LN + gate GEMM + sigmoid + head ----
    fused_k<<<MTOK/128, 512, SMEM_F>>>(x, norm_w, norm_b, p_wtb, head_w, head_b,
                                       (float*)d_out);
}